// round 5
// baseline (speedup 1.0000x reference)
#include <cuda_runtime.h>

typedef unsigned long long u64;

__device__ __forceinline__ u64 pk2(float lo, float hi) {
    u64 r;
    asm("mov.b64 %0, {%1, %2};" : "=l"(r)
        : "r"(__float_as_uint(lo)), "r"(__float_as_uint(hi)));
    return r;
}
__device__ __forceinline__ u64 ffma2(u64 a, u64 b, u64 c) {
    u64 d;
    asm("fma.rn.f32x2 %0, %1, %2, %3;" : "=l"(d) : "l"(a), "l"(b), "l"(c));
    return d;
}
__device__ __forceinline__ float f2lo(u64 v) { return __uint_as_float((unsigned)v); }
__device__ __forceinline__ float f2hi(u64 v) { return __uint_as_float((unsigned)(v >> 32)); }
__device__ __forceinline__ u64 d2u(double d) { return (u64)__double_as_longlong(d); }

// x: [B,1,7,7,7,7]  w1:[2,1,3,3,3,3] b1:[2]  w2:[4,2,3,3,3,3] b2:[4]
// out: [B, 4*81]
__global__ __launch_bounds__(64)
void fused4d_kernel(const float* __restrict__ x,
                    const float* __restrict__ w1, const float* __restrict__ b1,
                    const float* __restrict__ w2, const float* __restrict__ b2,
                    float* __restrict__ out, int nsamp)
{
    // x tile: u = L*7+D plane-row group, stride 60 floats (240B).
    // idx(u, r, c) = u*60 + r*8 + c.  Span per u = 54 < 60 (no overlap);
    // 60u mod 32 banks cycles all 8 float4 positions (conflict spread).
    __shared__ __align__(16) float  xs[2][2944];
    // h1: channel-paired (c0,c1) float2, rows of 5 padded to 6 (48B stride)
    __shared__ __align__(16) float2 h1[2][750];
    __shared__ __align__(16) float2 w1p[9][10];     // [plane][tap(pad)] = (oc0,oc1)
    __shared__ __align__(16) float2 w2p[4][9][10];  // [oc][plane][tap(pad)] = (ic0,ic1)
    __shared__ __align__(16) float2 b1p;
    __shared__ float b2s[4];

    const int t  = threadIdx.x;
    const int s0 = blockIdx.x * 2;

    // ---- weights -> smem ----
    for (int i = t; i < 81; i += 64) {
        int pl = i / 9, tp = i - pl * 9;
        w1p[pl][tp] = make_float2(w1[i], w1[81 + i]);
    }
    for (int i = t; i < 324; i += 64) {
        int oc = i / 81, rr = i - oc * 81;
        int pl = rr / 9, tp = rr - pl * 9;
        w2p[oc][pl][tp] = make_float2(w2[oc * 162 + rr], w2[oc * 162 + 81 + rr]);
    }
    if (t == 0) b1p = make_float2(b1[0], b1[1]);
    if (t < 4)  b2s[t] = b2[t];

    // ---- stage x: stride-60 padded rows ----
    {
        int nsm = nsamp - s0; if (nsm > 2) nsm = 2;
        for (int s = 0; s < nsm; s++) {
            const float* xb = x + (size_t)(s0 + s) * 2401;
            for (int i = t; i < 2401; i += 64) {
                int q = i / 7, c = i - q * 7;
                int u = q / 7, r = q - u * 7;
                xs[s][u * 60 + r * 8 + c] = xb[i];
            }
        }
    }
    __syncthreads();

    // ================= layer 1 =================
    // 25 threads/sample: thread=(l,d); all 5x5 (h,w) outputs, channels in f32x2.
    if (t < 50 && s0 + t / 25 < nsamp) {
        const int s   = t / 25;
        const int tid = t - s * 25;
        const int l   = tid / 5, d = tid - (tid / 5) * 5;

        const float* xb = &xs[s][0];
        const u64 bb = d2u(*(const double*)&b1p);
        u64 acc[5][5];
        #pragma unroll
        for (int h = 0; h < 5; h++)
            #pragma unroll
            for (int p = 0; p < 5; p++) acc[h][p] = bb;

        #pragma unroll
        for (int i = 0; i < 3; i++)
        #pragma unroll
        for (int j = 0; j < 3; j++) {
            const int u = (l + i) * 7 + (d + j);
            const float* pb = xb + u * 60;
            const int pl = i * 3 + j;

            // 9 channel-paired weights via vector loads (broadcast)
            u64 wr[9];
            {
                const double2* wv = (const double2*)&w1p[pl][0];
                double2 a0 = wv[0], a1 = wv[1], a2 = wv[2], a3 = wv[3];
                wr[0] = d2u(a0.x); wr[1] = d2u(a0.y);
                wr[2] = d2u(a1.x); wr[3] = d2u(a1.y);
                wr[4] = d2u(a2.x); wr[5] = d2u(a2.y);
                wr[6] = d2u(a3.x); wr[7] = d2u(a3.y);
                wr[8] = d2u(*(const double*)&w1p[pl][8]);
            }

            #pragma unroll
            for (int r = 0; r < 7; r++) {
                const float4* rp = (const float4*)(pb + r * 8);
                float4 v0 = rp[0], v1 = rp[1];
                u64 xx[7];
                xx[0] = pk2(v0.x, v0.x); xx[1] = pk2(v0.y, v0.y);
                xx[2] = pk2(v0.z, v0.z); xx[3] = pk2(v0.w, v0.w);
                xx[4] = pk2(v1.x, v1.x); xx[5] = pk2(v1.y, v1.y);
                xx[6] = pk2(v1.z, v1.z);
                #pragma unroll
                for (int k = 0; k < 3; k++) {
                    const int h = r - k;
                    if (h >= 0 && h <= 4) {
                        #pragma unroll
                        for (int m = 0; m < 3; m++) {
                            const u64 w = wr[k * 3 + m];
                            #pragma unroll
                            for (int p = 0; p < 5; p++)
                                acc[h][p] = ffma2(xx[p + m], w, acc[h][p]);
                        }
                    }
                }
            }
        }

        // relu + channel-paired store (rows of 6 float2)
        const int v = l * 5 + d;
        #pragma unroll
        for (int h = 0; h < 5; h++) {
            float2* hb = &h1[s][(v * 5 + h) * 6];
            #pragma unroll
            for (int p = 0; p < 5; p++)
                hb[p] = make_float2(fmaxf(f2lo(acc[h][p]), 0.f),
                                    fmaxf(f2hi(acc[h][p]), 0.f));
        }
    }
    __syncthreads();

    // ================= layer 2 =================
    // 27 threads/sample: thread=(l,d,h); computes 4 oc x 3 w.
    // hh operands loaded directly as f32x2 (c0,c1) -- zero pk2.
    if (t < 54 && s0 + t / 27 < nsamp) {
        const int s   = t / 27;
        const int tid = t - s * 27;
        const int l = tid / 9, d = (tid / 3) % 3, h = tid % 3;

        u64 acc[4][3];
        #pragma unroll
        for (int oc = 0; oc < 4; oc++) {
            u64 ini = pk2(b2s[oc], 0.f);
            #pragma unroll
            for (int p = 0; p < 3; p++) acc[oc][p] = ini;
        }

        #pragma unroll
        for (int i = 0; i < 3; i++)
        #pragma unroll
        for (int j = 0; j < 3; j++) {
            const int v  = (l + i) * 5 + (d + j);
            const int pl = i * 3 + j;

            // 3 rows of 5 channel-paired values each
            u64 hh[3][5];
            #pragma unroll
            for (int k = 0; k < 3; k++) {
                const float2* rb = &h1[s][(v * 5 + h + k) * 6];
                double2 a0 = ((const double2*)rb)[0];
                double2 a1 = ((const double2*)rb)[1];
                double  a2 = *(const double*)(rb + 4);
                hh[k][0] = d2u(a0.x); hh[k][1] = d2u(a0.y);
                hh[k][2] = d2u(a1.x); hh[k][3] = d2u(a1.y);
                hh[k][4] = d2u(a2);
            }

            #pragma unroll
            for (int oc = 0; oc < 4; oc++) {
                u64 wr[9];
                {
                    const double2* wv = (const double2*)&w2p[oc][pl][0];
                    double2 a0 = wv[0], a1 = wv[1], a2 = wv[2], a3 = wv[3];
                    wr[0] = d2u(a0.x); wr[1] = d2u(a0.y);
                    wr[2] = d2u(a1.x); wr[3] = d2u(a1.y);
                    wr[4] = d2u(a2.x); wr[5] = d2u(a2.y);
                    wr[6] = d2u(a3.x); wr[7] = d2u(a3.y);
                    wr[8] = d2u(*(const double*)&w2p[oc][pl][8]);
                }
                #pragma unroll
                for (int k = 0; k < 3; k++)
                #pragma unroll
                for (int m = 0; m < 3; m++) {
                    const u64 w = wr[k * 3 + m];
                    #pragma unroll
                    for (int p = 0; p < 3; p++)
                        acc[oc][p] = ffma2(hh[k][p + m], w, acc[oc][p]);
                }
            }
        }

        float* ob = out + (size_t)(s0 + s) * 324;
        const int pb = ((l * 3 + d) * 3 + h) * 3;
        #pragma unroll
        for (int oc = 0; oc < 4; oc++)
            #pragma unroll
            for (int p = 0; p < 3; p++)
                ob[oc * 81 + pb + p] =
                    fmaxf(f2lo(acc[oc][p]) + f2hi(acc[oc][p]), 0.f);
    }
}

extern "C" void kernel_launch(void* const* d_in, const int* in_sizes, int n_in,
                              void* d_out, int out_size) {
    const float* x  = (const float*)d_in[0];
    const float* w1 = (const float*)d_in[1];
    const float* b1 = (const float*)d_in[2];
    const float* w2 = (const float*)d_in[3];
    const float* b2 = (const float*)d_in[4];
    float* out = (float*)d_out;

    const int n = in_sizes[0] / 2401;        // B
    const int blocks = (n + 1) / 2;          // 2 samples / 64-thread block
    fused4d_kernel<<<blocks, 64>>>(x, w1, b1, w2, b2, out, n);
}

// round 6
// speedup vs baseline: 1.1800x; 1.1800x over previous
#include <cuda_runtime.h>

typedef unsigned long long u64;

__device__ __forceinline__ u64 pk2(float lo, float hi) {
    u64 r;
    asm("mov.b64 %0, {%1, %2};" : "=l"(r)
        : "r"(__float_as_uint(lo)), "r"(__float_as_uint(hi)));
    return r;
}
__device__ __forceinline__ u64 ffma2(u64 a, u64 b, u64 c) {
    u64 d;
    asm("fma.rn.f32x2 %0, %1, %2, %3;" : "=l"(d) : "l"(a), "l"(b), "l"(c));
    return d;
}
__device__ __forceinline__ float f2lo(u64 v) { return __uint_as_float((unsigned)v); }
__device__ __forceinline__ float f2hi(u64 v) { return __uint_as_float((unsigned)(v >> 32)); }
__device__ __forceinline__ u64 d2u(double d) { return (u64)__double_as_longlong(d); }

#define MAX_B 16384
// h1 scratch: [sample][pos(l*25+d*5+h)][w] channel-paired (c0,c1) float2
__device__ float2 g_h1[(size_t)MAX_B * 625];

// ================= kernel 1: layer 1 =================
// 2 samples / 256-thr block. thread=(l,d,h) in 5^3 (125/128 lanes),
// computes 5 w outputs x 2 channels packed in f32x2.
__global__ __launch_bounds__(256)
void l1_kernel(const float* __restrict__ x,
               const float* __restrict__ w1, const float* __restrict__ b1,
               int nsamp)
{
    __shared__ float  xs[2][2401];
    __shared__ __align__(16) float2 w1p[9][10];   // [plane][tap pad] (oc0,oc1)
    __shared__ float2 b1p;

    const int t  = threadIdx.x;
    const int s0 = blockIdx.x * 2;

    for (int i = t; i < 81; i += 256) {
        int pl = i / 9, tp = i - pl * 9;
        w1p[pl][tp] = make_float2(w1[i], w1[81 + i]);
    }
    if (t == 0) b1p = make_float2(b1[0], b1[1]);

    {
        int nsm = nsamp - s0; if (nsm > 2) nsm = 2;
        if (nsm == 2) {
            const float2* xb = (const float2*)(x + (size_t)s0 * 2401);
            float2* xd = (float2*)&xs[0][0];
            for (int i = t; i < 2401; i += 256) xd[i] = xb[i];
        } else if (nsm == 1) {
            const float* xb = x + (size_t)s0 * 2401;
            for (int i = t; i < 2401; i += 256) xs[0][i] = xb[i];
        }
    }
    __syncthreads();

    const int s   = t >> 7;       // warps 0-3: sample0, warps 4-7: sample1
    const int tid = t & 127;
    if (tid < 125 && s0 + s < nsamp) {
        const int l = tid / 25, d = (tid / 5) % 5, h = tid % 5;
        const float* xb = &xs[s][0] + d * 49 + h * 7;

        const u64 bb = d2u(*(const double*)&b1p);
        u64 acc[5];
        #pragma unroll
        for (int p = 0; p < 5; p++) acc[p] = bb;

        #pragma unroll
        for (int i = 0; i < 3; i++)
        #pragma unroll
        for (int j = 0; j < 3; j++) {
            const int pl = i * 3 + j;
            u64 wr[9];
            {
                const double2* wv = (const double2*)&w1p[pl][0];
                double2 a0 = wv[0], a1 = wv[1], a2 = wv[2], a3 = wv[3];
                wr[0] = d2u(a0.x); wr[1] = d2u(a0.y);
                wr[2] = d2u(a1.x); wr[3] = d2u(a1.y);
                wr[4] = d2u(a2.x); wr[5] = d2u(a2.y);
                wr[6] = d2u(a3.x); wr[7] = d2u(a3.y);
                wr[8] = d2u(*(const double*)&w1p[pl][8]);
            }
            const float* pb = xb + (l + i) * 343 + j * 49;
            #pragma unroll
            for (int k = 0; k < 3; k++) {
                const float* rp = pb + k * 7;
                u64 xx[7];
                #pragma unroll
                for (int q = 0; q < 7; q++) { float v = rp[q]; xx[q] = pk2(v, v); }
                #pragma unroll
                for (int m = 0; m < 3; m++) {
                    const u64 w = wr[k * 3 + m];
                    #pragma unroll
                    for (int p = 0; p < 5; p++)
                        acc[p] = ffma2(xx[p + m], w, acc[p]);
                }
            }
        }

        float2* hb = &g_h1[(size_t)(s0 + s) * 625 + (size_t)tid * 5];
        #pragma unroll
        for (int p = 0; p < 5; p++)
            hb[p] = make_float2(fmaxf(f2lo(acc[p]), 0.f),
                                fmaxf(f2hi(acc[p]), 0.f));
    }
}

// ================= kernel 2: layer 2 =================
// 4 samples / 224-thr block. thread=(pos in 3^3, ocpair) (216/224 lanes),
// computes 3 w x 2 oc; f32x2 lanes = (ic0,ic1) partials.
__global__ __launch_bounds__(224)
void l2_kernel(const float* __restrict__ w2, const float* __restrict__ b2,
               float* __restrict__ out, int nsamp)
{
    __shared__ __align__(16) float2 h1s[4][625];
    __shared__ __align__(16) float2 w2p[4][9][10]; // [oc][plane][tap pad] (ic0,ic1)
    __shared__ float b2s[4];

    const int t  = threadIdx.x;
    const int s0 = blockIdx.x * 4;

    for (int i = t; i < 324; i += 224) {
        int oc = i / 81, rr = i - oc * 81;
        int pl = rr / 9, tp = rr - pl * 9;
        w2p[oc][pl][tp] = make_float2(w2[oc * 162 + rr], w2[oc * 162 + 81 + rr]);
    }
    if (t < 4) b2s[t] = b2[t];

    {
        int nsm = nsamp - s0; if (nsm > 4) nsm = 4;
        int tot = nsm * 625;
        const float2* hg = &g_h1[(size_t)s0 * 625];
        for (int i = t; i < tot; i += 224) {
            int s = i / 625, r = i - s * 625;
            h1s[s][r] = hg[i];
        }
    }
    __syncthreads();

    const int s   = t / 54;
    const int tid = t - s * 54;
    if (t < 216 && s0 + s < nsamp) {
        const int pos = tid >> 1, ocp = tid & 1;
        const int l = pos / 9, d = (pos / 3) % 3, h = pos % 3;
        const int oc0 = 2 * ocp;

        u64 acc[2][3];
        #pragma unroll
        for (int c = 0; c < 2; c++) {
            u64 ini = pk2(b2s[oc0 + c], 0.f);
            #pragma unroll
            for (int p = 0; p < 3; p++) acc[c][p] = ini;
        }

        #pragma unroll
        for (int i = 0; i < 3; i++)
        #pragma unroll
        for (int j = 0; j < 3; j++) {
            const int pl = i * 3 + j;
            u64 wr[2][9];
            #pragma unroll
            for (int c = 0; c < 2; c++) {
                const double2* wv = (const double2*)&w2p[oc0 + c][pl][0];
                double2 a0 = wv[0], a1 = wv[1], a2 = wv[2], a3 = wv[3];
                wr[c][0] = d2u(a0.x); wr[c][1] = d2u(a0.y);
                wr[c][2] = d2u(a1.x); wr[c][3] = d2u(a1.y);
                wr[c][4] = d2u(a2.x); wr[c][5] = d2u(a2.y);
                wr[c][6] = d2u(a3.x); wr[c][7] = d2u(a3.y);
                wr[c][8] = d2u(*(const double*)&w2p[oc0 + c][pl][8]);
            }

            const float2* vb = &h1s[s][((l + i) * 25 + (d + j) * 5 + h) * 5];
            #pragma unroll
            for (int k = 0; k < 3; k++) {
                const double* rp = (const double*)(vb + k * 5);
                u64 hh[5];
                #pragma unroll
                for (int q = 0; q < 5; q++) hh[q] = d2u(rp[q]);
                #pragma unroll
                for (int m = 0; m < 3; m++)
                #pragma unroll
                for (int c = 0; c < 2; c++) {
                    const u64 w = wr[c][k * 3 + m];
                    #pragma unroll
                    for (int p = 0; p < 3; p++)
                        acc[c][p] = ffma2(hh[p + m], w, acc[c][p]);
                }
            }
        }

        float* ob = out + (size_t)(s0 + s) * 324;
        const int pb = ((l * 3 + d) * 3 + h) * 3;
        #pragma unroll
        for (int c = 0; c < 2; c++)
            #pragma unroll
            for (int p = 0; p < 3; p++)
                ob[(oc0 + c) * 81 + pb + p] =
                    fmaxf(f2lo(acc[c][p]) + f2hi(acc[c][p]), 0.f);
    }
}

extern "C" void kernel_launch(void* const* d_in, const int* in_sizes, int n_in,
                              void* d_out, int out_size) {
    const float* x  = (const float*)d_in[0];
    const float* w1 = (const float*)d_in[1];
    const float* b1 = (const float*)d_in[2];
    const float* w2 = (const float*)d_in[3];
    const float* b2 = (const float*)d_in[4];
    float* out = (float*)d_out;

    int n = in_sizes[0] / 2401;              // B
    if (n > MAX_B) n = MAX_B;
    l1_kernel<<<(n + 1) / 2, 256>>>(x, w1, b1, n);
    l2_kernel<<<(n + 3) / 4, 224>>>(w2, b2, out, n);
}

// round 7
// speedup vs baseline: 1.3300x; 1.1271x over previous
#include <cuda_runtime.h>

typedef unsigned long long u64;

__device__ __forceinline__ u64 pk2(float lo, float hi) {
    u64 r;
    asm("mov.b64 %0, {%1, %2};" : "=l"(r)
        : "r"(__float_as_uint(lo)), "r"(__float_as_uint(hi)));
    return r;
}
__device__ __forceinline__ u64 ffma2(u64 a, u64 b, u64 c) {
    u64 d;
    asm("fma.rn.f32x2 %0, %1, %2, %3;" : "=l"(d) : "l"(a), "l"(b), "l"(c));
    return d;
}
__device__ __forceinline__ float f2lo(u64 v) { return __uint_as_float((unsigned)v); }
__device__ __forceinline__ float f2hi(u64 v) { return __uint_as_float((unsigned)(v >> 32)); }
__device__ __forceinline__ u64 d2u(double d) { return (u64)__double_as_longlong(d); }

#define MAX_B 16384
// h1 scratch: [sample][pos(l*25+d*5+h)][w] channel-paired (c0,c1) float2
__device__ float2 g_h1[(size_t)MAX_B * 625];

// ================= kernel 1: layer 1 =================
// 5 samples / 128-thr block; thread=(l,d) computes all 5x5 (h,w) outputs,
// channels (oc0,oc1) packed in f32x2. 125/128 lanes active.
__global__ __launch_bounds__(128)
void l1_kernel(const float* __restrict__ x,
               const float* __restrict__ w1, const float* __restrict__ b1,
               int nsamp)
{
    __shared__ float xs[5][2401];
    __shared__ __align__(16) float2 w1p[9][10];   // [plane][tap pad] (oc0,oc1)
    __shared__ float2 b1p;

    const int t  = threadIdx.x;
    const int s0 = blockIdx.x * 5;

    for (int i = t; i < 81; i += 128) {
        int pl = i / 9, tp = i - pl * 9;
        w1p[pl][tp] = make_float2(w1[i], w1[81 + i]);
    }
    if (t == 0) b1p = make_float2(b1[0], b1[1]);

    {
        int nsm = nsamp - s0; if (nsm > 5) nsm = 5;
        int lim = nsm * 2401;
        const float* xb = x + (size_t)s0 * 2401;
        for (int i = t; i < lim; i += 128) ((float*)xs)[i] = xb[i];
    }
    __syncthreads();

    const int s   = t / 25;
    const int tid = t - s * 25;
    if (t < 125 && s0 + s < nsamp) {
        const int l = tid / 5, d = tid - (tid / 5) * 5;

        const u64 bb = d2u(*(const double*)&b1p);
        u64 acc[5][5];
        #pragma unroll
        for (int h = 0; h < 5; h++)
            #pragma unroll
            for (int p = 0; p < 5; p++) acc[h][p] = bb;

        #pragma unroll
        for (int i = 0; i < 3; i++)
        #pragma unroll
        for (int j = 0; j < 3; j++) {
            const int pl = i * 3 + j;
            u64 wr[9];
            {
                const double2* wv = (const double2*)&w1p[pl][0];
                double2 a0 = wv[0], a1 = wv[1], a2 = wv[2], a3 = wv[3];
                wr[0] = d2u(a0.x); wr[1] = d2u(a0.y);
                wr[2] = d2u(a1.x); wr[3] = d2u(a1.y);
                wr[4] = d2u(a2.x); wr[5] = d2u(a2.y);
                wr[6] = d2u(a3.x); wr[7] = d2u(a3.y);
                wr[8] = d2u(*(const double*)&w1p[pl][8]);
            }
            const float* pb = &xs[s][0] + (l + i) * 343 + (d + j) * 49;
            #pragma unroll
            for (int r = 0; r < 7; r++) {
                const float* rp = pb + r * 7;
                u64 xx[7];
                #pragma unroll
                for (int q = 0; q < 7; q++) { float v = rp[q]; xx[q] = pk2(v, v); }
                #pragma unroll
                for (int k = 0; k < 3; k++) {
                    const int h = r - k;
                    if (h >= 0 && h <= 4) {
                        #pragma unroll
                        for (int m = 0; m < 3; m++) {
                            const u64 w = wr[k * 3 + m];
                            #pragma unroll
                            for (int p = 0; p < 5; p++)
                                acc[h][p] = ffma2(xx[p + m], w, acc[h][p]);
                        }
                    }
                }
            }
        }

        // 25 contiguous float2 per thread (pos = l*25+d*5+h, w)
        float2* hb = &g_h1[(size_t)(s0 + s) * 625 + (size_t)(l * 25 + d * 5) * 5];
        #pragma unroll
        for (int h = 0; h < 5; h++)
            #pragma unroll
            for (int p = 0; p < 5; p++)
                hb[h * 5 + p] = make_float2(fmaxf(f2lo(acc[h][p]), 0.f),
                                            fmaxf(f2hi(acc[h][p]), 0.f));
    }
}

// ================= kernel 2: layer 2 =================
// 9 samples / 256-thr block; thread=(pos in 3^3) computes all 4 oc x 3 w.
// f32x2 lanes = (ic0,ic1) partials; weights warp-uniform (broadcast).
__global__ __launch_bounds__(256)
void l2_kernel(const float* __restrict__ w2, const float* __restrict__ b2,
               float* __restrict__ out, int nsamp)
{
    __shared__ float2 h1s[9][625];
    __shared__ __align__(16) float2 w2p[4][9][10]; // [oc][plane][tap pad] (ic0,ic1)
    __shared__ float b2s[4];

    const int t  = threadIdx.x;
    const int s0 = blockIdx.x * 9;

    for (int i = t; i < 324; i += 256) {
        int oc = i / 81, rr = i - oc * 81;
        int pl = rr / 9, tp = rr - pl * 9;
        w2p[oc][pl][tp] = make_float2(w2[oc * 162 + rr], w2[oc * 162 + 81 + rr]);
    }
    if (t < 4) b2s[t] = b2[t];

    {
        int nsm = nsamp - s0; if (nsm > 9) nsm = 9;
        int tot = nsm * 625;
        const float2* hg = &g_h1[(size_t)s0 * 625];
        for (int i = t; i < tot; i += 256) ((float2*)h1s)[i] = hg[i];
    }
    __syncthreads();

    const int s   = t / 27;
    const int tid = t - s * 27;
    if (t < 243 && s0 + s < nsamp) {
        const int l = tid / 9, d = (tid / 3) % 3, h = tid % 3;

        u64 acc[4][3];
        #pragma unroll
        for (int oc = 0; oc < 4; oc++) {
            u64 ini = pk2(b2s[oc], 0.f);
            #pragma unroll
            for (int p = 0; p < 3; p++) acc[oc][p] = ini;
        }

        #pragma unroll
        for (int i = 0; i < 3; i++)
        #pragma unroll
        for (int j = 0; j < 3; j++) {
            const int pl = i * 3 + j;
            const float2* vb = &h1s[s][((l + i) * 25 + (d + j) * 5 + h) * 5];

            u64 hh[3][5];
            #pragma unroll
            for (int k = 0; k < 3; k++) {
                const double* rp = (const double*)(vb + k * 5);
                #pragma unroll
                for (int q = 0; q < 5; q++) hh[k][q] = d2u(rp[q]);
            }

            #pragma unroll
            for (int oc = 0; oc < 4; oc++) {
                u64 wr[9];
                {
                    const double2* wv = (const double2*)&w2p[oc][pl][0];
                    double2 a0 = wv[0], a1 = wv[1], a2 = wv[2], a3 = wv[3];
                    wr[0] = d2u(a0.x); wr[1] = d2u(a0.y);
                    wr[2] = d2u(a1.x); wr[3] = d2u(a1.y);
                    wr[4] = d2u(a2.x); wr[5] = d2u(a2.y);
                    wr[6] = d2u(a3.x); wr[7] = d2u(a3.y);
                    wr[8] = d2u(*(const double*)&w2p[oc][pl][8]);
                }
                #pragma unroll
                for (int k = 0; k < 3; k++)
                #pragma unroll
                for (int m = 0; m < 3; m++) {
                    const u64 w = wr[k * 3 + m];
                    #pragma unroll
                    for (int p = 0; p < 3; p++)
                        acc[oc][p] = ffma2(hh[k][p + m], w, acc[oc][p]);
                }
            }
        }

        float* ob = out + (size_t)(s0 + s) * 324;
        const int pb = ((l * 3 + d) * 3 + h) * 3;
        #pragma unroll
        for (int oc = 0; oc < 4; oc++)
            #pragma unroll
            for (int p = 0; p < 3; p++)
                ob[oc * 81 + pb + p] =
                    fmaxf(f2lo(acc[oc][p]) + f2hi(acc[oc][p]), 0.f);
    }
}

extern "C" void kernel_launch(void* const* d_in, const int* in_sizes, int n_in,
                              void* d_out, int out_size) {
    const float* x  = (const float*)d_in[0];
    const float* w1 = (const float*)d_in[1];
    const float* b1 = (const float*)d_in[2];
    const float* w2 = (const float*)d_in[3];
    const float* b2 = (const float*)d_in[4];
    float* out = (float*)d_out;

    int n = in_sizes[0] / 2401;              // B
    if (n > MAX_B) n = MAX_B;
    l1_kernel<<<(n + 4) / 5, 128>>>(x, w1, b1, n);
    l2_kernel<<<(n + 8) / 9, 256>>>(w2, b2, out, n);
}